// round 6
// baseline (speedup 1.0000x reference)
#include <cuda_runtime.h>

#define BB 16
#define LL 4096
#define DD 64
#define NS 16
#define CC 64          // number of chunks
#define LC 64          // chunk length  (CC*LC == LL)
#define LOG2E 1.4426950408889634f

typedef unsigned long long ull;

// ---------------- scratch (device globals; no allocation) ----------------
__device__ float g_delta[BB*LL*DD];        // 16 MB
__device__ float g_Bt[BB*LL*NS];           // 4 MB
__device__ float g_Ct[BB*LL*NS];           // 4 MB  (pre-scaled by 1/A in fast mode)
__device__ float g_aggP[BB*CC*DD*NS];      // 4 MB  per-chunk aggregate decay
__device__ float g_aggH[BB*CC*DD*NS];      // 4 MB  per-chunk local hend
__device__ float g_incH[BB*CC*DD*NS];      // 4 MB  inclusive prefix h
__device__ int   g_flag[BB*CC];            // lookback flags
__device__ float g_y[BB*LL*DD];            // 16 MB (only used if W_out != I)
__device__ float g_A2[DD*NS];
__device__ float g_invA[DD*NS];
__device__ float g_A2row[NS];
__device__ float g_iArow[NS];
__device__ int   g_fast;                   // A rows d-independent AND geometric in n
__device__ int   g_ident;                  // W_out == I, b_out == 0

__device__ __forceinline__ float ex2f(float a){
    float r; asm("ex2.approx.ftz.f32 %0, %1;" : "=f"(r) : "f"(a)); return r;
}
// ---- packed fp32x2 helpers ----
__device__ __forceinline__ ull pk2(float lo, float hi){
    ull r; asm("mov.b64 %0, {%1,%2};" : "=l"(r) : "f"(lo), "f"(hi)); return r;
}
__device__ __forceinline__ void upk2(float& lo, float& hi, ull a){
    asm("mov.b64 {%0,%1}, %2;" : "=f"(lo), "=f"(hi) : "l"(a));
}
__device__ __forceinline__ ull mul2(ull a, ull b){
    ull r; asm("mul.rn.f32x2 %0, %1, %2;" : "=l"(r) : "l"(a), "l"(b)); return r;
}
__device__ __forceinline__ ull add2(ull a, ull b){
    ull r; asm("add.rn.f32x2 %0, %1, %2;" : "=l"(r) : "l"(a), "l"(b)); return r;
}
__device__ __forceinline__ ull fma2(ull a, ull b, ull c){
    ull r; asm("fma.rn.f32x2 %0, %1, %2, %3;" : "=l"(r) : "l"(a), "l"(b), "l"(c)); return r;
}
__device__ __forceinline__ ull neg2(ull a){ return a ^ 0x8000000080000000ULL; }

__device__ __forceinline__ void cpa16(unsigned dst, const void* src){
    asm volatile("cp.async.cg.shared.global [%0], [%1], 16;" :: "r"(dst), "l"(src));
}
__device__ __forceinline__ void cpa_commit(){ asm volatile("cp.async.commit_group;"); }
template<int N> __device__ __forceinline__ void cpa_wait(){
    asm volatile("cp.async.wait_group %0;" :: "n"(N) : "memory");
}
__device__ __forceinline__ int ld_acquire(const int* p){
    int v; asm volatile("ld.acquire.gpu.global.b32 %0, [%1];" : "=r"(v) : "l"(p)); return v;
}
__device__ __forceinline__ void st_release(int* p, int v){
    asm volatile("st.release.gpu.global.b32 [%0], %1;" :: "l"(p), "r"(v));
}

__device__ __forceinline__ float softplusf(float z){
    return (z > 15.f) ? z : __logf(1.f + __expf(z));
}

// ---------------- prep (also resets lookback flags every launch) -----------
__global__ __launch_bounds__(256) void prep_kernel(const float* __restrict__ A_log,
                            const float* __restrict__ Wout,
                            const float* __restrict__ bout)
{
    int tid = threadIdx.x;
    if (blockIdx.x == 0){
        __shared__ int s_dind, s_geo;
        if (tid == 0){ s_dind = 1; s_geo = 1; }
        __syncthreads();
        for (int i = tid; i < BB*CC; i += blockDim.x) g_flag[i] = 0;
        for (int i = tid; i < DD*NS; i += blockDim.x){
            float al = A_log[i];
            float ar = -__expf(al);
            g_A2[i]   = ar * LOG2E;
            g_invA[i] = 1.0f / ar;
            if (__float_as_int(al) != __float_as_int(A_log[i & (NS-1)]))
                atomicAnd(&s_dind, 0);
        }
        if (tid < NS){
            float ar0 = -__expf(A_log[0]);
            float arn = -__expf(A_log[tid]);
            float pred = ar0 * (float)(tid + 1);
            if (fabsf(arn - pred) > 1e-5f * fabsf(arn)) atomicAnd(&s_geo, 0);
            g_A2row[tid] = arn * LOG2E;
            g_iArow[tid] = 1.0f / arn;
        }
        __syncthreads();
        if (tid == 0) g_fast = s_dind & s_geo;
    } else {
        __shared__ int ok;
        if (tid == 0) ok = 1;
        __syncthreads();
        int bad = 0;
        for (int i = tid; i < DD*DD; i += blockDim.x){
            float expect = ((i / DD) == (i % DD)) ? 1.0f : 0.0f;
            if (Wout[i] != expect) bad = 1;
        }
        for (int i = tid; i < DD; i += blockDim.x)
            if (bout[i] != 0.0f) bad = 1;
        if (bad) atomicAnd(&ok, 0);
        __syncthreads();
        if (tid == 0) g_ident = ok;
    }
}

// ---------------- projections (token-paired f32x2 GEMM) --------------------
__global__ __launch_bounds__(256) void proj_kernel(const float* __restrict__ x,
    const float* __restrict__ Wd, const float* __restrict__ bd,
    const float* __restrict__ WB, const float* __restrict__ WC)
{
    __shared__ float xs[64*64];     // [token][k]
    __shared__ float Wall[64*96];   // [k][j]
    int tid = threadIdx.x;
    size_t tokBase = (size_t)blockIdx.x * 64;

    const float4* xg  = (const float4*)(x + tokBase*DD);
    float4* xs4 = (float4*)xs;
    #pragma unroll
    for (int i = 0; i < 4; i++) xs4[tid + i*256] = xg[tid + i*256];

    for (int i = tid; i < 64*96; i += 256){
        int k = i / 96, j = i % 96;
        float v;
        if (j < 64)      v = Wd[j*64 + k];
        else if (j < 80) v = WB[(j-64)*64 + k];
        else             v = WC[(j-80)*64 + k];
        Wall[i] = v;
    }
    __syncthreads();

    int warp = tid >> 5, lane = tid & 31;
    ull accp[4][3];
    #pragma unroll
    for (int p = 0; p < 4; p++){ accp[p][0]=0; accp[p][1]=0; accp[p][2]=0; }

    const float4* xr = (const float4*)(xs + (warp*8)*64);

    #pragma unroll 4
    for (int k4 = 0; k4 < 16; k4++){
        ull wp[4][3];
        #pragma unroll
        for (int kk = 0; kk < 4; kk++){
            float w0 = Wall[(k4*4+kk)*96 + lane];
            float w1 = Wall[(k4*4+kk)*96 + lane + 32];
            float w2 = Wall[(k4*4+kk)*96 + lane + 64];
            wp[kk][0] = pk2(w0, w0);
            wp[kk][1] = pk2(w1, w1);
            wp[kk][2] = pk2(w2, w2);
        }
        #pragma unroll
        for (int p = 0; p < 4; p++){
            float4 xa = xr[(2*p)*16 + k4];
            float4 xb = xr[(2*p+1)*16 + k4];
            ull xp0 = pk2(xa.x, xb.x);
            ull xp1 = pk2(xa.y, xb.y);
            ull xp2 = pk2(xa.z, xb.z);
            ull xp3 = pk2(xa.w, xb.w);
            #pragma unroll
            for (int j = 0; j < 3; j++){
                accp[p][j] = fma2(xp0, wp[0][j], accp[p][j]);
                accp[p][j] = fma2(xp1, wp[1][j], accp[p][j]);
                accp[p][j] = fma2(xp2, wp[2][j], accp[p][j]);
                accp[p][j] = fma2(xp3, wp[3][j], accp[p][j]);
            }
        }
    }

    float b0 = bd[lane], b1 = bd[lane+32];
    float ctscale = 1.0f;
    if (lane >= 16 && g_fast) ctscale = g_iArow[lane - 16];

    #pragma unroll
    for (int p = 0; p < 4; p++){
        size_t t0 = tokBase + warp*8 + 2*p;
        size_t t1 = t0 + 1;
        float a0l, a0h, a1l, a1h, a2l, a2h;
        upk2(a0l, a0h, accp[p][0]);
        upk2(a1l, a1h, accp[p][1]);
        upk2(a2l, a2h, accp[p][2]);
        g_delta[t0*DD + lane]      = softplusf(a0l + b0);
        g_delta[t1*DD + lane]      = softplusf(a0h + b0);
        g_delta[t0*DD + lane + 32] = softplusf(a1l + b1);
        g_delta[t1*DD + lane + 32] = softplusf(a1h + b1);
        if (lane < 16){
            g_Bt[t0*NS + lane] = a2l;
            g_Bt[t1*NS + lane] = a2h;
        } else {
            g_Ct[t0*NS + lane - 16] = a2l * ctscale;
            g_Ct[t1*NS + lane - 16] = a2h * ctscale;
        }
    }
}

// ---------------- fused single-pass scan with decoupled lookback ----------
// grid 1024 (bid = c*BB + b), block 128 (thread = (d, half); 8 states each).
__global__ __launch_bounds__(128) void scan_fused_kernel(const float* __restrict__ x,
    const float* __restrict__ Dskip, float* __restrict__ out)
{
    __shared__ float sD[LC*DD];   // 16 KB
    __shared__ float sX[LC*DD];   // 16 KB
    __shared__ float sB[LC*NS];   // 4 KB
    __shared__ float sC[LC*NS];   // 4 KB
    int bid = blockIdx.x;
    int c = bid >> 4, b = bid & (BB-1);
    int tid = threadIdx.x;
    int d = tid >> 1, hf = tid & 1;
    size_t t0 = (size_t)b*LL + (size_t)c*LC;

    // ---- stage entire chunk ----
    {
        unsigned aD = (unsigned)__cvta_generic_to_shared(sD);
        unsigned aX = (unsigned)__cvta_generic_to_shared(sX);
        unsigned aB = (unsigned)__cvta_generic_to_shared(sB);
        unsigned aC = (unsigned)__cvta_generic_to_shared(sC);
        const float* dsrc = g_delta + t0*DD;
        const float* xsrc = x       + t0*DD;
        const float* bsrc = g_Bt    + t0*NS;
        const float* csrc = g_Ct    + t0*NS;
        #pragma unroll
        for (int i = 0; i < (LC*DD/4)/128; i++){
            cpa16(aD + (tid + i*128)*16, dsrc + (tid + i*128)*4);
            cpa16(aX + (tid + i*128)*16, xsrc + (tid + i*128)*4);
        }
        #pragma unroll
        for (int i = 0; i < (LC*NS/4)/128; i++){
            cpa16(aB + (tid + i*128)*16, bsrc + (tid + i*128)*4);
            cpa16(aC + (tid + i*128)*16, csrc + (tid + i*128)*4);
        }
        cpa_commit();
        cpa_wait<0>();
    }
    __syncthreads();

    size_t vidx = (size_t)bid*1024 + (size_t)d*NS + (size_t)hf*8;
    float dsk = Dskip[d];
    bool write_y = (g_ident == 0);
    float* yp = g_y + t0*DD + d;
    float* op = out + t0*DD + d;

    if (g_fast){
        float a20 = g_A2row[0];
        // ---- pass A: local scan from 0 -> hend + P ----
        ull h[4];
        #pragma unroll
        for (int q = 0; q < 4; q++) h[q] = 0;
        float sd = 0.f;
        #pragma unroll 2
        for (int t = 0; t < LC; t++){
            float dv = sD[t*DD + d];
            float xv = sX[t*DD + d];
            sd += dv;
            float r  = ex2f(dv * a20);
            float r2 = r * r;
            float r4 = r2 * r2;
            float r9 = r4 * r4 * r;
            float rm = hf ? r9 : r;
            ull e  = pk2(rm, rm * r);
            ull rr = pk2(r2, r2);
            ull xpk = pk2(xv, xv);
            const ull* bt2 = (const ull*)(&sB[t*NS]) + hf*4;
            #pragma unroll
            for (int q = 0; q < 4; q++){
                ull p = mul2(bt2[q], xpk);
                h[q] = fma2(e, add2(h[q], p), neg2(p));
                if (q < 3) e = mul2(e, rr);
            }
        }
        ull pe[4];
        {
            float rho  = ex2f(a20 * sd);
            float rho2 = rho * rho;
            float rho4 = rho2 * rho2;
            float rho9 = rho4 * rho4 * rho;
            float rhom = hf ? rho9 : rho;
            ull e  = pk2(rhom, rhom * rho);
            ull rr = pk2(rho2, rho2);
            #pragma unroll
            for (int q = 0; q < 4; q++){
                pe[q] = e;
                if (q < 3) e = mul2(e, rr);
            }
        }

        // ---- lookback: resolve exclusive prefix acc ----
        ull acc[4];
        #pragma unroll
        for (int q = 0; q < 4; q++) acc[q] = 0;
        if (c > 0){
            ull* aP = (ull*)(g_aggP + vidx);
            ull* aH = (ull*)(g_aggH + vidx);
            #pragma unroll
            for (int q = 0; q < 4; q++){ aP[q] = pe[q]; aH[q] = h[q]; }
            __threadfence();
            __syncthreads();
            if (tid == 0) st_release(&g_flag[bid], 1);

            ull accP[4];
            #pragma unroll
            for (int q = 0; q < 4; q++) accP[q] = pk2(1.f, 1.f);
            int j = bid - BB;
            while (true){
                int f = ld_acquire(&g_flag[j]);
                while (f < 1){ __nanosleep(40); f = ld_acquire(&g_flag[j]); }
                size_t jb = (size_t)j*1024 + (size_t)d*NS + (size_t)hf*8;
                if (f >= 2){
                    const ull* iH = (const ull*)(g_incH + jb);
                    #pragma unroll
                    for (int q = 0; q < 4; q++) acc[q] = fma2(accP[q], iH[q], acc[q]);
                    break;
                } else {
                    const ull* jH = (const ull*)(g_aggH + jb);
                    const ull* jP = (const ull*)(g_aggP + jb);
                    #pragma unroll
                    for (int q = 0; q < 4; q++){
                        acc[q]  = fma2(accP[q], jH[q], acc[q]);
                        accP[q] = mul2(accP[q], jP[q]);
                    }
                    j -= BB;
                }
            }
            ull* iH = (ull*)(g_incH + vidx);
            #pragma unroll
            for (int q = 0; q < 4; q++) iH[q] = fma2(pe[q], acc[q], h[q]);
            __threadfence();
            __syncthreads();
            if (tid == 0) st_release(&g_flag[bid], 2);
        } else {
            ull* iH = (ull*)(g_incH + vidx);
            #pragma unroll
            for (int q = 0; q < 4; q++) iH[q] = h[q];
            __threadfence();
            __syncthreads();
            if (tid == 0) st_release(&g_flag[bid], 2);
        }

        // ---- pass B: rescan from h0 = acc, emit y ----
        ull hh[4];
        #pragma unroll
        for (int q = 0; q < 4; q++) hh[q] = acc[q];
        #pragma unroll 2
        for (int t = 0; t < LC; t++){
            float dv = sD[t*DD + d];
            float xv = sX[t*DD + d];
            float r  = ex2f(dv * a20);
            float r2 = r * r;
            float r4 = r2 * r2;
            float r9 = r4 * r4 * r;
            float rm = hf ? r9 : r;
            ull e  = pk2(rm, rm * r);
            ull rr = pk2(r2, r2);
            ull xpk = pk2(xv, xv);
            const ull* bt2 = (const ull*)(&sB[t*NS]) + hf*4;
            const ull* ct2 = (const ull*)(&sC[t*NS]) + hf*4;
            ull y2 = 0;
            #pragma unroll
            for (int q = 0; q < 4; q++){
                ull p = mul2(bt2[q], xpk);
                hh[q] = fma2(e, add2(hh[q], p), neg2(p));
                y2 = fma2(ct2[q], hh[q], y2);
                if (q < 3) e = mul2(e, rr);
            }
            float ylo, yhi;
            upk2(ylo, yhi, y2);
            float part = ylo + yhi;
            part += __shfl_xor_sync(0xFFFFFFFFu, part, 1);
            if (hf == 0){
                float y = fmaf(dsk, xv, part);
                op[(size_t)t*DD] = y;
                if (write_y) yp[(size_t)t*DD] = y;
            }
        }
    } else {
        // -------- general path (scalar, 8 states/thread) --------
        float A2[8], iA[8];
        {
            const float4* a4 = (const float4*)(g_A2 + d*NS + hf*8);
            const float4* i4 = (const float4*)(g_invA + d*NS + hf*8);
            #pragma unroll
            for (int q = 0; q < 2; q++){
                float4 a = a4[q]; float4 ii = i4[q];
                A2[4*q+0]=a.x; A2[4*q+1]=a.y; A2[4*q+2]=a.z; A2[4*q+3]=a.w;
                iA[4*q+0]=ii.x; iA[4*q+1]=ii.y; iA[4*q+2]=ii.z; iA[4*q+3]=ii.w;
            }
        }
        float h[8];
        #pragma unroll
        for (int n = 0; n < 8; n++) h[n] = 0.f;
        float sd = 0.f;
        for (int t = 0; t < LC; t++){
            float dv = sD[t*DD + d];
            float xv = sX[t*DD + d];
            sd += dv;
            const float* bt = &sB[t*NS] + hf*8;
            #pragma unroll
            for (int n = 0; n < 8; n++){
                float e = ex2f(dv * A2[n]);
                float p = iA[n] * (bt[n] * xv);
                h[n] = fmaf(e, h[n] + p, -p);
            }
        }
        float P[8];
        #pragma unroll
        for (int n = 0; n < 8; n++) P[n] = ex2f(A2[n] * sd);

        float acc[8];
        #pragma unroll
        for (int n = 0; n < 8; n++) acc[n] = 0.f;
        if (c > 0){
            #pragma unroll
            for (int n = 0; n < 8; n++){
                g_aggP[vidx + n] = P[n];
                g_aggH[vidx + n] = h[n];
            }
            __threadfence();
            __syncthreads();
            if (tid == 0) st_release(&g_flag[bid], 1);

            float accP[8];
            #pragma unroll
            for (int n = 0; n < 8; n++) accP[n] = 1.f;
            int j = bid - BB;
            while (true){
                int f = ld_acquire(&g_flag[j]);
                while (f < 1){ __nanosleep(40); f = ld_acquire(&g_flag[j]); }
                size_t jb = (size_t)j*1024 + (size_t)d*NS + (size_t)hf*8;
                if (f >= 2){
                    #pragma unroll
                    for (int n = 0; n < 8; n++)
                        acc[n] = fmaf(accP[n], g_incH[jb + n], acc[n]);
                    break;
                } else {
                    #pragma unroll
                    for (int n = 0; n < 8; n++){
                        acc[n]  = fmaf(accP[n], g_aggH[jb + n], acc[n]);
                        accP[n] = accP[n] * g_aggP[jb + n];
                    }
                    j -= BB;
                }
            }
            #pragma unroll
            for (int n = 0; n < 8; n++)
                g_incH[vidx + n] = fmaf(P[n], acc[n], h[n]);
            __threadfence();
            __syncthreads();
            if (tid == 0) st_release(&g_flag[bid], 2);
        } else {
            #pragma unroll
            for (int n = 0; n < 8; n++) g_incH[vidx + n] = h[n];
            __threadfence();
            __syncthreads();
            if (tid == 0) st_release(&g_flag[bid], 2);
        }

        float hh[8];
        #pragma unroll
        for (int n = 0; n < 8; n++) hh[n] = acc[n];
        for (int t = 0; t < LC; t++){
            float dv = sD[t*DD + d];
            float xv = sX[t*DD + d];
            const float* bt = &sB[t*NS] + hf*8;
            const float* ct = &sC[t*NS] + hf*8;
            float part = 0.f;
            #pragma unroll
            for (int n = 0; n < 8; n++){
                float e = ex2f(dv * A2[n]);
                float p = iA[n] * (bt[n] * xv);
                hh[n] = fmaf(e, hh[n] + p, -p);
                part = fmaf(ct[n], hh[n], part);
            }
            part += __shfl_xor_sync(0xFFFFFFFFu, part, 1);
            if (hf == 0){
                float y = fmaf(dsk, xv, part);
                op[(size_t)t*DD] = y;
                if (write_y) yp[(size_t)t*DD] = y;
            }
        }
    }
}

// ---------------- final W_out GEMM (skipped when W_out == I, b == 0) -----
__global__ __launch_bounds__(256) void outgemm_kernel(const float* __restrict__ Wout,
    const float* __restrict__ bout, float* __restrict__ out)
{
    if (g_ident) return;
    __shared__ float Wt[64*64];
    __shared__ float ys[8][64];
    int tid = threadIdx.x;
    for (int i = tid; i < 4096; i += 256){
        int k = i >> 6, e = i & 63;
        Wt[k*64 + e] = Wout[e*64 + k];
    }
    __syncthreads();
    int warp = tid >> 5, lane = tid & 31;
    size_t tokBase = (size_t)blockIdx.x * 64;
    for (int tk = 0; tk < 8; tk++){
        size_t tg = tokBase + warp*8 + tk;
        ys[warp][lane]      = g_y[tg*64 + lane];
        ys[warp][lane + 32] = g_y[tg*64 + lane + 32];
        __syncwarp();
        float a0 = bout[lane], a1 = bout[lane+32];
        #pragma unroll
        for (int k = 0; k < 64; k++){
            float yv = ys[warp][k];
            a0 = fmaf(yv, Wt[k*64 + lane],      a0);
            a1 = fmaf(yv, Wt[k*64 + lane + 32], a1);
        }
        __syncwarp();
        out[tg*64 + lane]      = a0;
        out[tg*64 + lane + 32] = a1;
    }
}

// ---------------- launch ----------------
extern "C" void kernel_launch(void* const* d_in, const int* in_sizes, int n_in,
                              void* d_out, int out_size)
{
    const float* x     = (const float*)d_in[0];
    const float* A_log = (const float*)d_in[1];
    const float* Dskip = (const float*)d_in[2];
    const float* Wout  = (const float*)d_in[3];
    const float* bout  = (const float*)d_in[4];
    const float* Wd    = (const float*)d_in[5];
    const float* bd    = (const float*)d_in[6];
    const float* WB    = (const float*)d_in[7];
    const float* WC    = (const float*)d_in[8];
    float* out = (float*)d_out;

    prep_kernel<<<2, 256>>>(A_log, Wout, bout);
    proj_kernel<<<BB*LL/64, 256>>>(x, Wd, bd, WB, WC);
    scan_fused_kernel<<<BB*CC, 128>>>(x, Dskip, out);
    outgemm_kernel<<<BB*LL/64, 256>>>(Wout, bout, out);
}

// round 7
// speedup vs baseline: 1.0206x; 1.0206x over previous
#include <cuda_runtime.h>

#define BB 16
#define LL 4096
#define DD 64
#define NS 16
#define CC 32          // number of chunks
#define LC 128         // chunk length  (CC*LC == LL)
#define STG 32         // tokens per smem stage
#define NSTG (LC/STG)  // stages per chunk
#define NPROJ (BB*LL/64)   // 1024 proj blocks
#define LOG2E 1.4426950408889634f

typedef unsigned long long ull;

// ---------------- scratch (device globals; no allocation) ----------------
__device__ float g_delta[BB*LL*DD];        // 16 MB
__device__ float g_Bt[BB*LL*NS];           // 4 MB
__device__ float g_Ct[BB*LL*NS];           // 4 MB (raw; 1/A folded at scan3 staging)
__device__ float g_P   [BB*CC*DD*NS];      // 2 MB
__device__ float g_hend[BB*CC*DD*NS];      // 2 MB
__device__ float g_y[BB*LL*DD];            // 16 MB (only used if W_out != I)
__device__ float g_A2[DD*NS];
__device__ float g_invA[DD*NS];
__device__ float g_A2row[NS];
__device__ float g_iArow[NS];
__device__ int   g_fast;                   // A rows d-independent AND geometric in n
__device__ int   g_ident;                  // W_out == I, b_out == 0

__device__ __forceinline__ float ex2f(float a){
    float r; asm("ex2.approx.ftz.f32 %0, %1;" : "=f"(r) : "f"(a)); return r;
}
// ---- packed fp32x2 helpers ----
__device__ __forceinline__ ull pk2(float lo, float hi){
    ull r; asm("mov.b64 %0, {%1,%2};" : "=l"(r) : "f"(lo), "f"(hi)); return r;
}
__device__ __forceinline__ void upk2(float& lo, float& hi, ull a){
    asm("mov.b64 {%0,%1}, %2;" : "=f"(lo), "=f"(hi) : "l"(a));
}
__device__ __forceinline__ ull mul2(ull a, ull b){
    ull r; asm("mul.rn.f32x2 %0, %1, %2;" : "=l"(r) : "l"(a), "l"(b)); return r;
}
__device__ __forceinline__ ull add2(ull a, ull b){
    ull r; asm("add.rn.f32x2 %0, %1, %2;" : "=l"(r) : "l"(a), "l"(b)); return r;
}
__device__ __forceinline__ ull fma2(ull a, ull b, ull c){
    ull r; asm("fma.rn.f32x2 %0, %1, %2, %3;" : "=l"(r) : "l"(a), "l"(b), "l"(c)); return r;
}
__device__ __forceinline__ ull neg2(ull a){ return a ^ 0x8000000080000000ULL; }

__device__ __forceinline__ void cpa16(unsigned dst, const void* src){
    asm volatile("cp.async.cg.shared.global [%0], [%1], 16;" :: "r"(dst), "l"(src));
}
__device__ __forceinline__ void cpa_commit(){ asm volatile("cp.async.commit_group;"); }
template<int N> __device__ __forceinline__ void cpa_wait(){
    asm volatile("cp.async.wait_group %0;" :: "n"(N) : "memory");
}

__device__ __forceinline__ float softplusf(float z){
    return (z > 15.f) ? z : __logf(1.f + __expf(z));
}

// ---------------- projections (+ merged prep in blocks NPROJ, NPROJ+1) ----
__global__ __launch_bounds__(256) void proj_kernel(const float* __restrict__ x,
    const float* __restrict__ Wd, const float* __restrict__ bd,
    const float* __restrict__ WB, const float* __restrict__ WC,
    const float* __restrict__ A_log,
    const float* __restrict__ Wout, const float* __restrict__ bout)
{
    int tid = threadIdx.x;
    if (blockIdx.x >= NPROJ){
        if (blockIdx.x == NPROJ){
            __shared__ int s_dind, s_geo;
            if (tid == 0){ s_dind = 1; s_geo = 1; }
            __syncthreads();
            for (int i = tid; i < DD*NS; i += blockDim.x){
                float al = A_log[i];
                float ar = -__expf(al);
                g_A2[i]   = ar * LOG2E;
                g_invA[i] = 1.0f / ar;
                if (__float_as_int(al) != __float_as_int(A_log[i & (NS-1)]))
                    atomicAnd(&s_dind, 0);
            }
            if (tid < NS){
                float ar0 = -__expf(A_log[0]);
                float arn = -__expf(A_log[tid]);
                float pred = ar0 * (float)(tid + 1);
                if (fabsf(arn - pred) > 1e-5f * fabsf(arn)) atomicAnd(&s_geo, 0);
                g_A2row[tid] = arn * LOG2E;
                g_iArow[tid] = 1.0f / arn;
            }
            __syncthreads();
            if (tid == 0) g_fast = s_dind & s_geo;
        } else {
            __shared__ int ok;
            if (tid == 0) ok = 1;
            __syncthreads();
            int bad = 0;
            for (int i = tid; i < DD*DD; i += blockDim.x){
                float expect = ((i / DD) == (i % DD)) ? 1.0f : 0.0f;
                if (Wout[i] != expect) bad = 1;
            }
            for (int i = tid; i < DD; i += blockDim.x)
                if (bout[i] != 0.0f) bad = 1;
            if (bad) atomicAnd(&ok, 0);
            __syncthreads();
            if (tid == 0) g_ident = ok;
        }
        return;
    }

    __shared__ float xs[64*64];     // [token][k]
    __shared__ float Wall[64*96];   // [k][j]
    size_t tokBase = (size_t)blockIdx.x * 64;

    const float4* xg  = (const float4*)(x + tokBase*DD);
    float4* xs4 = (float4*)xs;
    #pragma unroll
    for (int i = 0; i < 4; i++) xs4[tid + i*256] = xg[tid + i*256];

    for (int i = tid; i < 64*96; i += 256){
        int k = i / 96, j = i % 96;
        float v;
        if (j < 64)      v = Wd[j*64 + k];
        else if (j < 80) v = WB[(j-64)*64 + k];
        else             v = WC[(j-80)*64 + k];
        Wall[i] = v;
    }
    __syncthreads();

    int warp = tid >> 5, lane = tid & 31;
    ull accp[4][3];
    #pragma unroll
    for (int p = 0; p < 4; p++){ accp[p][0]=0; accp[p][1]=0; accp[p][2]=0; }

    const float4* xr = (const float4*)(xs + (warp*8)*64);

    #pragma unroll 4
    for (int k4 = 0; k4 < 16; k4++){
        ull wp[4][3];
        #pragma unroll
        for (int kk = 0; kk < 4; kk++){
            float w0 = Wall[(k4*4+kk)*96 + lane];
            float w1 = Wall[(k4*4+kk)*96 + lane + 32];
            float w2 = Wall[(k4*4+kk)*96 + lane + 64];
            wp[kk][0] = pk2(w0, w0);
            wp[kk][1] = pk2(w1, w1);
            wp[kk][2] = pk2(w2, w2);
        }
        #pragma unroll
        for (int p = 0; p < 4; p++){
            float4 xa = xr[(2*p)*16 + k4];
            float4 xb = xr[(2*p+1)*16 + k4];
            ull xp0 = pk2(xa.x, xb.x);
            ull xp1 = pk2(xa.y, xb.y);
            ull xp2 = pk2(xa.z, xb.z);
            ull xp3 = pk2(xa.w, xb.w);
            #pragma unroll
            for (int j = 0; j < 3; j++){
                accp[p][j] = fma2(xp0, wp[0][j], accp[p][j]);
                accp[p][j] = fma2(xp1, wp[1][j], accp[p][j]);
                accp[p][j] = fma2(xp2, wp[2][j], accp[p][j]);
                accp[p][j] = fma2(xp3, wp[3][j], accp[p][j]);
            }
        }
    }

    float b0 = bd[lane], b1 = bd[lane+32];

    #pragma unroll
    for (int p = 0; p < 4; p++){
        size_t t0 = tokBase + warp*8 + 2*p;
        size_t t1 = t0 + 1;
        float a0l, a0h, a1l, a1h, a2l, a2h;
        upk2(a0l, a0h, accp[p][0]);
        upk2(a1l, a1h, accp[p][1]);
        upk2(a2l, a2h, accp[p][2]);
        g_delta[t0*DD + lane]      = softplusf(a0l + b0);
        g_delta[t1*DD + lane]      = softplusf(a0h + b0);
        g_delta[t0*DD + lane + 32] = softplusf(a1l + b1);
        g_delta[t1*DD + lane + 32] = softplusf(a1h + b1);
        if (lane < 16){
            g_Bt[t0*NS + lane] = a2l;
            g_Bt[t1*NS + lane] = a2h;
        } else {
            g_Ct[t0*NS + lane - 16] = a2l;
            g_Ct[t1*NS + lane - 16] = a2h;
        }
    }
}

// ---------------- pass 1: per-chunk local scan (h0 = 0) -> h_end, P -------
// grid (CC, BB), block 64 (thread = d). cp.async double-buffered staging.
__global__ __launch_bounds__(64) void scan1_kernel(const float* __restrict__ x)
{
    __shared__ float sD[2][STG*DD];   // 2 x 8 KB
    __shared__ float sX[2][STG*DD];   // 2 x 8 KB
    __shared__ float sB[2][STG*NS];   // 2 x 2 KB
    int b = blockIdx.y, c = blockIdx.x, d = threadIdx.x;
    size_t t0 = (size_t)b*LL + (size_t)c*LC;

    const float* dg = g_delta + t0*DD;
    const float* xg = x       + t0*DD;
    const float* bg = g_Bt    + t0*NS;

    auto load_stage = [&](int s, int bf){
        unsigned aD = (unsigned)__cvta_generic_to_shared(&sD[bf][0]);
        unsigned aX = (unsigned)__cvta_generic_to_shared(&sX[bf][0]);
        unsigned aB = (unsigned)__cvta_generic_to_shared(&sB[bf][0]);
        const float* dsrc = dg + (size_t)s*STG*DD;
        const float* xsrc = xg + (size_t)s*STG*DD;
        const float* bsrc = bg + (size_t)s*STG*NS;
        #pragma unroll
        for (int i = 0; i < (STG*DD/4)/64; i++){
            cpa16(aD + (d + i*64)*16, dsrc + (d + i*64)*4);
            cpa16(aX + (d + i*64)*16, xsrc + (d + i*64)*4);
        }
        #pragma unroll
        for (int i = 0; i < (STG*NS/4)/64; i++)
            cpa16(aB + (d + i*64)*16, bsrc + (d + i*64)*4);
        cpa_commit();
    };

    load_stage(0, 0);
    load_stage(1, 1);

    size_t base = (((size_t)(b*CC + c))*DD + d)*NS;

    if (g_fast){
        float a20 = g_A2row[0];
        ull h[8];
        #pragma unroll
        for (int q = 0; q < 8; q++) h[q] = 0;
        float sd = 0.f;
        for (int s = 0; s < NSTG; s++){
            if (s < NSTG-1) cpa_wait<1>(); else cpa_wait<0>();
            __syncthreads();
            int bf = s & 1;
            #pragma unroll 2
            for (int t = 0; t < STG; t++){
                float dv = sD[bf][t*DD + d];
                float xv = sX[bf][t*DD + d];
                sd += dv;
                float r  = ex2f(dv * a20);
                float r2 = r * r;
                ull e  = pk2(r, r2);
                ull rr = pk2(r2, r2);
                ull xpk = pk2(xv, xv);
                const ull* bt2 = (const ull*)(&sB[bf][t*NS]);
                #pragma unroll
                for (int q = 0; q < 8; q++){
                    ull p = mul2(bt2[q], xpk);
                    h[q] = fma2(e, add2(h[q], p), neg2(p));
                    if (q < 7) e = mul2(e, rr);
                }
            }
            __syncthreads();
            if (s + 2 < NSTG) load_stage(s+2, bf);
        }
        ull* he = (ull*)(g_hend + base);
        #pragma unroll
        for (int q = 0; q < 8; q++) he[q] = h[q];
        float rho  = ex2f(a20 * sd);
        float rho2 = rho * rho;
        ull pe  = pk2(rho, rho2);
        ull prr = pk2(rho2, rho2);
        ull* pg = (ull*)(g_P + base);
        #pragma unroll
        for (int q = 0; q < 8; q++){
            pg[q] = pe;
            if (q < 7) pe = mul2(pe, prr);
        }
    } else {
        float A2[NS], iA[NS], h[NS];
        const float4* a4 = (const float4*)(g_A2 + d*NS);
        const float4* i4 = (const float4*)(g_invA + d*NS);
        #pragma unroll
        for (int q = 0; q < 4; q++){
            float4 a = a4[q]; float4 ii = i4[q];
            A2[4*q+0]=a.x; A2[4*q+1]=a.y; A2[4*q+2]=a.z; A2[4*q+3]=a.w;
            iA[4*q+0]=ii.x; iA[4*q+1]=ii.y; iA[4*q+2]=ii.z; iA[4*q+3]=ii.w;
        }
        #pragma unroll
        for (int n = 0; n < NS; n++) h[n] = 0.f;
        float sd = 0.f;
        for (int s = 0; s < NSTG; s++){
            if (s < NSTG-1) cpa_wait<1>(); else cpa_wait<0>();
            __syncthreads();
            int bf = s & 1;
            for (int t = 0; t < STG; t++){
                float dv = sD[bf][t*DD + d];
                float xv = sX[bf][t*DD + d];
                sd += dv;
                const float* bt = &sB[bf][t*NS];
                #pragma unroll
                for (int n = 0; n < NS; n++){
                    float e = ex2f(dv * A2[n]);
                    float p = iA[n] * (bt[n] * xv);
                    h[n] = fmaf(e, h[n] + p, -p);
                }
            }
            __syncthreads();
            if (s + 2 < NSTG) load_stage(s+2, bf);
        }
        #pragma unroll
        for (int n = 0; n < NS; n++){
            g_hend[base+n] = h[n];
            g_P[base+n]    = ex2f(A2[n] * sd);
        }
    }
}

// ---------------- pass 3: inline lookback h0, rescan, emit y --------------
__global__ __launch_bounds__(64) void scan3_kernel(const float* __restrict__ x,
    const float* __restrict__ Dskip, float* __restrict__ out)
{
    __shared__ float sD[2][STG*DD];
    __shared__ float sX[2][STG*DD];
    __shared__ float sB[2][STG*NS];
    __shared__ float sC[2][STG*NS];
    int b = blockIdx.y, c = blockIdx.x, d = threadIdx.x;
    size_t t0 = (size_t)b*LL + (size_t)c*LC;

    const float* dg = g_delta + t0*DD;
    const float* xg = x       + t0*DD;
    const float* bg = g_Bt    + t0*NS;
    const float* cg = g_Ct    + t0*NS;

    auto load_stage = [&](int s, int bf){
        unsigned aD = (unsigned)__cvta_generic_to_shared(&sD[bf][0]);
        unsigned aX = (unsigned)__cvta_generic_to_shared(&sX[bf][0]);
        unsigned aB = (unsigned)__cvta_generic_to_shared(&sB[bf][0]);
        unsigned aC = (unsigned)__cvta_generic_to_shared(&sC[bf][0]);
        const float* dsrc = dg + (size_t)s*STG*DD;
        const float* xsrc = xg + (size_t)s*STG*DD;
        const float* bsrc = bg + (size_t)s*STG*NS;
        const float* csrc = cg + (size_t)s*STG*NS;
        #pragma unroll
        for (int i = 0; i < (STG*DD/4)/64; i++){
            cpa16(aD + (d + i*64)*16, dsrc + (d + i*64)*4);
            cpa16(aX + (d + i*64)*16, xsrc + (d + i*64)*4);
        }
        #pragma unroll
        for (int i = 0; i < (STG*NS/4)/64; i++){
            cpa16(aB + (d + i*64)*16, bsrc + (d + i*64)*4);
            cpa16(aC + (d + i*64)*16, csrc + (d + i*64)*4);
        }
        cpa_commit();
    };

    load_stage(0, 0);
    load_stage(1, 1);

    float dsk = Dskip[d];
    bool write_y = (g_ident == 0);

    float* yp = g_y + t0*DD + d;
    float* op = out + t0*DD + d;

    // lookback base: chunk j of this batch at + j*1024
    size_t lb = ((size_t)(b*CC))*DD*NS + (size_t)d*NS;

    if (g_fast){
        float a20 = g_A2row[0];
        // iA scale vector for sC staging: this thread always touches n = (d&3)*4 .. +3
        float4 ia4 = ((const float4*)g_iArow)[d & 3];

        // ---- inline lookback: h0 = scan of (P,hend) over chunks 0..c-1 ----
        ull h[8];
        #pragma unroll
        for (int q = 0; q < 8; q++) h[q] = 0;
        {
            int j = 0;
            for (; j + 2 <= c; j += 2){
                const ull* p0 = (const ull*)(g_P    + lb + (size_t)j*1024);
                const ull* e0 = (const ull*)(g_hend + lb + (size_t)j*1024);
                const ull* p1 = (const ull*)(g_P    + lb + (size_t)(j+1)*1024);
                const ull* e1 = (const ull*)(g_hend + lb + (size_t)(j+1)*1024);
                ull P0[8], E0[8], P1[8], E1[8];
                #pragma unroll
                for (int q = 0; q < 8; q++){ P0[q]=p0[q]; E0[q]=e0[q]; P1[q]=p1[q]; E1[q]=e1[q]; }
                #pragma unroll
                for (int q = 0; q < 8; q++){
                    h[q] = fma2(P0[q], h[q], E0[q]);
                    h[q] = fma2(P1[q], h[q], E1[q]);
                }
            }
            if (j < c){
                const ull* p0 = (const ull*)(g_P    + lb + (size_t)j*1024);
                const ull* e0 = (const ull*)(g_hend + lb + (size_t)j*1024);
                #pragma unroll
                for (int q = 0; q < 8; q++) h[q] = fma2(p0[q], h[q], e0[q]);
            }
        }

        for (int s = 0; s < NSTG; s++){
            if (s < NSTG-1) cpa_wait<1>(); else cpa_wait<0>();
            __syncthreads();
            int bf = s & 1;
            // fold 1/A into staged Ct (raw -> scaled)
            {
                float4* c4 = (float4*)&sC[bf][0];
                #pragma unroll
                for (int i = 0; i < (STG*NS/4)/64; i++){
                    float4 v = c4[d + i*64];
                    v.x *= ia4.x; v.y *= ia4.y; v.z *= ia4.z; v.w *= ia4.w;
                    c4[d + i*64] = v;
                }
            }
            __syncthreads();
            #pragma unroll 2
            for (int tl = 0; tl < STG; tl++){
                int t = s*STG + tl;
                float dv = sD[bf][tl*DD + d];
                float xv = sX[bf][tl*DD + d];
                float r  = ex2f(dv * a20);
                float r2 = r * r;
                ull e  = pk2(r, r2);
                ull rr = pk2(r2, r2);
                ull xpk = pk2(xv, xv);
                const ull* bt2 = (const ull*)(&sB[bf][tl*NS]);
                const ull* ct2 = (const ull*)(&sC[bf][tl*NS]);
                ull y2 = 0;
                #pragma unroll
                for (int q = 0; q < 8; q++){
                    ull p = mul2(bt2[q], xpk);
                    h[q] = fma2(e, add2(h[q], p), neg2(p));
                    y2 = fma2(ct2[q], h[q], y2);
                    if (q < 7) e = mul2(e, rr);
                }
                float ylo, yhi;
                upk2(ylo, yhi, y2);
                float y = fmaf(dsk, xv, ylo + yhi);
                op[(size_t)t*DD] = y;
                if (write_y) yp[(size_t)t*DD] = y;
            }
            __syncthreads();
            if (s + 2 < NSTG) load_stage(s+2, bf);
        }
    } else {
        float A2[NS], iA[NS], h[NS];
        const float4* a4 = (const float4*)(g_A2 + d*NS);
        const float4* i4 = (const float4*)(g_invA + d*NS);
        #pragma unroll
        for (int q = 0; q < 4; q++){
            float4 a = a4[q]; float4 ii = i4[q];
            A2[4*q+0]=a.x; A2[4*q+1]=a.y; A2[4*q+2]=a.z; A2[4*q+3]=a.w;
            iA[4*q+0]=ii.x; iA[4*q+1]=ii.y; iA[4*q+2]=ii.z; iA[4*q+3]=ii.w;
        }
        // ---- inline lookback (scalar) ----
        #pragma unroll
        for (int n = 0; n < NS; n++) h[n] = 0.f;
        {
            int j = 0;
            for (; j + 2 <= c; j += 2){
                const float* p0 = g_P    + lb + (size_t)j*1024;
                const float* e0 = g_hend + lb + (size_t)j*1024;
                const float* p1 = g_P    + lb + (size_t)(j+1)*1024;
                const float* e1 = g_hend + lb + (size_t)(j+1)*1024;
                float P0[NS], E0[NS], P1[NS], E1[NS];
                #pragma unroll
                for (int n = 0; n < NS; n++){ P0[n]=p0[n]; E0[n]=e0[n]; P1[n]=p1[n]; E1[n]=e1[n]; }
                #pragma unroll
                for (int n = 0; n < NS; n++){
                    h[n] = fmaf(P0[n], h[n], E0[n]);
                    h[n] = fmaf(P1[n], h[n], E1[n]);
                }
            }
            if (j < c){
                const float* p0 = g_P    + lb + (size_t)j*1024;
                const float* e0 = g_hend + lb + (size_t)j*1024;
                #pragma unroll
                for (int n = 0; n < NS; n++) h[n] = fmaf(p0[n], h[n], e0[n]);
            }
        }
        for (int s = 0; s < NSTG; s++){
            if (s < NSTG-1) cpa_wait<1>(); else cpa_wait<0>();
            __syncthreads();
            int bf = s & 1;
            for (int tl = 0; tl < STG; tl++){
                int t = s*STG + tl;
                float dv = sD[bf][tl*DD + d];
                float xv = sX[bf][tl*DD + d];
                const float* bt = &sB[bf][tl*NS];
                const float* ct = &sC[bf][tl*NS];
                float y = dsk * xv;
                #pragma unroll
                for (int n = 0; n < NS; n++){
                    float e = ex2f(dv * A2[n]);
                    float p = iA[n] * (bt[n] * xv);
                    h[n] = fmaf(e, h[n] + p, -p);
                    y = fmaf(ct[n], h[n], y);
                }
                op[(size_t)t*DD] = y;
                if (write_y) yp[(size_t)t*DD] = y;
            }
            __syncthreads();
            if (s + 2 < NSTG) load_stage(s+2, bf);
        }
    }
}

// ---------------- final W_out GEMM (skipped when W_out == I, b == 0) -----
__global__ __launch_bounds__(256) void outgemm_kernel(const float* __restrict__ Wout,
    const float* __restrict__ bout, float* __restrict__ out)
{
    if (g_ident) return;
    __shared__ float Wt[64*64];
    __shared__ float ys[8][64];
    int tid = threadIdx.x;
    for (int i = tid; i < 4096; i += 256){
        int k = i >> 6, e = i & 63;
        Wt[k*64 + e] = Wout[e*64 + k];
    }
    __syncthreads();
    int warp = tid >> 5, lane = tid & 31;
    size_t tokBase = (size_t)blockIdx.x * 64;
    for (int tk = 0; tk < 8; tk++){
        size_t tg = tokBase + warp*8 + tk;
        ys[warp][lane]      = g_y[tg*64 + lane];
        ys[warp][lane + 32] = g_y[tg*64 + lane + 32];
        __syncwarp();
        float a0 = bout[lane], a1 = bout[lane+32];
        #pragma unroll
        for (int k = 0; k < 64; k++){
            float yv = ys[warp][k];
            a0 = fmaf(yv, Wt[k*64 + lane],      a0);
            a1 = fmaf(yv, Wt[k*64 + lane + 32], a1);
        }
        __syncwarp();
        out[tg*64 + lane]      = a0;
        out[tg*64 + lane + 32] = a1;
    }
}

// ---------------- launch ----------------
extern "C" void kernel_launch(void* const* d_in, const int* in_sizes, int n_in,
                              void* d_out, int out_size)
{
    const float* x     = (const float*)d_in[0];
    const float* A_log = (const float*)d_in[1];
    const float* Dskip = (const float*)d_in[2];
    const float* Wout  = (const float*)d_in[3];
    const float* bout  = (const float*)d_in[4];
    const float* Wd    = (const float*)d_in[5];
    const float* bd    = (const float*)d_in[6];
    const float* WB    = (const float*)d_in[7];
    const float* WC    = (const float*)d_in[8];
    float* out = (float*)d_out;

    proj_kernel<<<NPROJ + 2, 256>>>(x, Wd, bd, WB, WC, A_log, Wout, bout);
    dim3 g(CC, BB);
    scan1_kernel<<<g, 64>>>(x);
    scan3_kernel<<<g, 64>>>(x, Dskip, out);
    outgemm_kernel<<<NPROJ, 256>>>(Wout, bout, out);
}

// round 8
// speedup vs baseline: 1.2491x; 1.2238x over previous
#include <cuda_runtime.h>

#define BB 16
#define LL 4096
#define DD 64
#define NS 16
#define CC 32          // number of chunks
#define LC 128         // chunk length  (CC*LC == LL)
#define STG 32         // tokens per smem stage
#define NSTG (LC/STG)  // stages per chunk
#define NPROJ (BB*LL/64)   // 1024 proj tiles
#define LOG2E 1.4426950408889634f

typedef unsigned long long ull;

// ---------------- scratch (device globals; no allocation) ----------------
__device__ float g_delta[BB*LL*DD];        // 16 MB
__device__ float g_Bt[BB*LL*NS];           // 4 MB
__device__ float g_Ct[BB*LL*NS];           // 4 MB  (pre-scaled by 1/A in fast mode)
__device__ float g_P   [BB*CC*DD*NS];      // 2 MB
__device__ float g_hend[BB*CC*DD*NS];      // 2 MB
__device__ float g_h0  [BB*CC*DD*NS];      // 2 MB
__device__ float g_y[BB*LL*DD];            // 16 MB (only used if W_out != I)
__device__ float g_A2[DD*NS];
__device__ float g_invA[DD*NS];
__device__ float g_A2row[NS];
__device__ float g_iArow[NS];
__device__ int   g_fast;                   // A rows d-independent AND geometric in n
__device__ int   g_ident;                  // W_out == I, b_out == 0

__device__ __forceinline__ float ex2f(float a){
    float r; asm("ex2.approx.ftz.f32 %0, %1;" : "=f"(r) : "f"(a)); return r;
}
// ---- packed fp32x2 helpers ----
__device__ __forceinline__ ull pk2(float lo, float hi){
    ull r; asm("mov.b64 %0, {%1,%2};" : "=l"(r) : "f"(lo), "f"(hi)); return r;
}
__device__ __forceinline__ void upk2(float& lo, float& hi, ull a){
    asm("mov.b64 {%0,%1}, %2;" : "=f"(lo), "=f"(hi) : "l"(a));
}
__device__ __forceinline__ ull mul2(ull a, ull b){
    ull r; asm("mul.rn.f32x2 %0, %1, %2;" : "=l"(r) : "l"(a), "l"(b)); return r;
}
__device__ __forceinline__ ull add2(ull a, ull b){
    ull r; asm("add.rn.f32x2 %0, %1, %2;" : "=l"(r) : "l"(a), "l"(b)); return r;
}
__device__ __forceinline__ ull fma2(ull a, ull b, ull c){
    ull r; asm("fma.rn.f32x2 %0, %1, %2, %3;" : "=l"(r) : "l"(a), "l"(b), "l"(c)); return r;
}
__device__ __forceinline__ ull neg2(ull a){ return a ^ 0x8000000080000000ULL; }

__device__ __forceinline__ void cpa16(unsigned dst, const void* src){
    asm volatile("cp.async.cg.shared.global [%0], [%1], 16;" :: "r"(dst), "l"(src));
}
__device__ __forceinline__ void cpa_commit(){ asm volatile("cp.async.commit_group;"); }
template<int N> __device__ __forceinline__ void cpa_wait(){
    asm volatile("cp.async.wait_group %0;" :: "n"(N) : "memory");
}

__device__ __forceinline__ float softplusf(float z){
    return (z > 15.f) ? z : __logf(1.f + __expf(z));
}

// ---------------- projections (+ merged prep blocks) -----------------------
// Blocks [0, NPROJ): token-tile GEMM. Block NPROJ: A-structure prep.
// Block NPROJ+1: W_out identity check. Data blocks re-derive the fast-mode
// predicate locally (same computation as prep -> same verdict) so Ct scaling
// has no cross-block ordering dependency.
__global__ __launch_bounds__(256) void proj_kernel(const float* __restrict__ x,
    const float* __restrict__ Wd, const float* __restrict__ bd,
    const float* __restrict__ WB, const float* __restrict__ WC,
    const float* __restrict__ A_log,
    const float* __restrict__ Wout, const float* __restrict__ bout)
{
    int tid = threadIdx.x;
    if (blockIdx.x >= NPROJ){
        if (blockIdx.x == NPROJ){
            __shared__ int s_dind, s_geo;
            if (tid == 0){ s_dind = 1; s_geo = 1; }
            __syncthreads();
            for (int i = tid; i < DD*NS; i += blockDim.x){
                float al = A_log[i];
                float ar = -__expf(al);
                g_A2[i]   = ar * LOG2E;
                g_invA[i] = 1.0f / ar;
                if (__float_as_int(al) != __float_as_int(A_log[i & (NS-1)]))
                    atomicAnd(&s_dind, 0);
            }
            if (tid < NS){
                float ar0 = -__expf(A_log[0]);
                float arn = -__expf(A_log[tid]);
                float pred = ar0 * (float)(tid + 1);
                if (fabsf(arn - pred) > 1e-5f * fabsf(arn)) atomicAnd(&s_geo, 0);
                g_A2row[tid] = arn * LOG2E;
                g_iArow[tid] = 1.0f / arn;
            }
            __syncthreads();
            if (tid == 0) g_fast = s_dind & s_geo;
        } else {
            __shared__ int ok;
            if (tid == 0) ok = 1;
            __syncthreads();
            int bad = 0;
            for (int i = tid; i < DD*DD; i += blockDim.x){
                float expect = ((i / DD) == (i % DD)) ? 1.0f : 0.0f;
                if (Wout[i] != expect) bad = 1;
            }
            for (int i = tid; i < DD; i += blockDim.x)
                if (bout[i] != 0.0f) bad = 1;
            if (bad) atomicAnd(&ok, 0);
            __syncthreads();
            if (tid == 0) g_ident = ok;
        }
        return;
    }

    // ---- local fast-mode predicate (identical math to prep block) ----
    int abad = 0;
    for (int i = tid; i < DD*NS; i += 256)
        if (__float_as_int(A_log[i]) != __float_as_int(A_log[i & (NS-1)]))
            abad = 1;
    {
        float ar0 = -__expf(A_log[0]);
        int n = tid & (NS-1);
        float arn = -__expf(A_log[n]);
        float pred = ar0 * (float)(n + 1);
        if (fabsf(arn - pred) > 1e-5f * fabsf(arn)) abad = 1;
    }
    int lfast = !__syncthreads_or(abad);

    __shared__ float xs[64*64];     // [token][k]
    __shared__ float Wall[64*96];   // [k][j]
    size_t tokBase = (size_t)blockIdx.x * 64;

    const float4* xg  = (const float4*)(x + tokBase*DD);
    float4* xs4 = (float4*)xs;
    #pragma unroll
    for (int i = 0; i < 4; i++) xs4[tid + i*256] = xg[tid + i*256];

    for (int i = tid; i < 64*96; i += 256){
        int k = i / 96, j = i % 96;
        float v;
        if (j < 64)      v = Wd[j*64 + k];
        else if (j < 80) v = WB[(j-64)*64 + k];
        else             v = WC[(j-80)*64 + k];
        Wall[i] = v;
    }
    __syncthreads();

    int warp = tid >> 5, lane = tid & 31;
    ull accp[4][3];
    #pragma unroll
    for (int p = 0; p < 4; p++){ accp[p][0]=0; accp[p][1]=0; accp[p][2]=0; }

    const float4* xr = (const float4*)(xs + (warp*8)*64);

    #pragma unroll 4
    for (int k4 = 0; k4 < 16; k4++){
        ull wp[4][3];
        #pragma unroll
        for (int kk = 0; kk < 4; kk++){
            float w0 = Wall[(k4*4+kk)*96 + lane];
            float w1 = Wall[(k4*4+kk)*96 + lane + 32];
            float w2 = Wall[(k4*4+kk)*96 + lane + 64];
            wp[kk][0] = pk2(w0, w0);
            wp[kk][1] = pk2(w1, w1);
            wp[kk][2] = pk2(w2, w2);
        }
        #pragma unroll
        for (int p = 0; p < 4; p++){
            float4 xa = xr[(2*p)*16 + k4];
            float4 xb = xr[(2*p+1)*16 + k4];
            ull xp0 = pk2(xa.x, xb.x);
            ull xp1 = pk2(xa.y, xb.y);
            ull xp2 = pk2(xa.z, xb.z);
            ull xp3 = pk2(xa.w, xb.w);
            #pragma unroll
            for (int j = 0; j < 3; j++){
                accp[p][j] = fma2(xp0, wp[0][j], accp[p][j]);
                accp[p][j] = fma2(xp1, wp[1][j], accp[p][j]);
                accp[p][j] = fma2(xp2, wp[2][j], accp[p][j]);
                accp[p][j] = fma2(xp3, wp[3][j], accp[p][j]);
            }
        }
    }

    float b0 = bd[lane], b1 = bd[lane+32];
    float ctscale = 1.0f;
    if (lane >= 16 && lfast) ctscale = 1.0f / (-__expf(A_log[lane - 16]));

    #pragma unroll
    for (int p = 0; p < 4; p++){
        size_t t0 = tokBase + warp*8 + 2*p;
        size_t t1 = t0 + 1;
        float a0l, a0h, a1l, a1h, a2l, a2h;
        upk2(a0l, a0h, accp[p][0]);
        upk2(a1l, a1h, accp[p][1]);
        upk2(a2l, a2h, accp[p][2]);
        g_delta[t0*DD + lane]      = softplusf(a0l + b0);
        g_delta[t1*DD + lane]      = softplusf(a0h + b0);
        g_delta[t0*DD + lane + 32] = softplusf(a1l + b1);
        g_delta[t1*DD + lane + 32] = softplusf(a1h + b1);
        if (lane < 16){
            g_Bt[t0*NS + lane] = a2l;
            g_Bt[t1*NS + lane] = a2h;
        } else {
            g_Ct[t0*NS + lane - 16] = a2l * ctscale;
            g_Ct[t1*NS + lane - 16] = a2h * ctscale;
        }
    }
}

// ---------------- pass 1: per-chunk local scan (h0 = 0) -> h_end, P -------
// grid (CC, BB), block 64 (thread = d). cp.async double-buffered staging.
__global__ __launch_bounds__(64) void scan1_kernel(const float* __restrict__ x)
{
    __shared__ __align__(16) float sD[2][STG*DD];   // 2 x 8 KB
    __shared__ __align__(16) float sX[2][STG*DD];   // 2 x 8 KB
    __shared__ __align__(16) float sB[2][STG*NS];   // 2 x 2 KB
    int b = blockIdx.y, c = blockIdx.x, d = threadIdx.x;
    size_t t0 = (size_t)b*LL + (size_t)c*LC;

    const float* dg = g_delta + t0*DD;
    const float* xg = x       + t0*DD;
    const float* bg = g_Bt    + t0*NS;

    auto load_stage = [&](int s, int bf){
        unsigned aD = (unsigned)__cvta_generic_to_shared(&sD[bf][0]);
        unsigned aX = (unsigned)__cvta_generic_to_shared(&sX[bf][0]);
        unsigned aB = (unsigned)__cvta_generic_to_shared(&sB[bf][0]);
        const float* dsrc = dg + (size_t)s*STG*DD;
        const float* xsrc = xg + (size_t)s*STG*DD;
        const float* bsrc = bg + (size_t)s*STG*NS;
        #pragma unroll
        for (int i = 0; i < (STG*DD/4)/64; i++){
            cpa16(aD + (d + i*64)*16, dsrc + (d + i*64)*4);
            cpa16(aX + (d + i*64)*16, xsrc + (d + i*64)*4);
        }
        #pragma unroll
        for (int i = 0; i < (STG*NS/4)/64; i++)
            cpa16(aB + (d + i*64)*16, bsrc + (d + i*64)*4);
        cpa_commit();
    };

    load_stage(0, 0);
    load_stage(1, 1);

    size_t base = (((size_t)(b*CC + c))*DD + d)*NS;

    if (g_fast){
        float a20 = g_A2row[0];
        ull h[8];
        #pragma unroll
        for (int q = 0; q < 8; q++) h[q] = 0;
        float sd = 0.f;
        for (int s = 0; s < NSTG; s++){
            if (s < NSTG-1) cpa_wait<1>(); else cpa_wait<0>();
            __syncthreads();
            int bf = s & 1;
            #pragma unroll 2
            for (int t = 0; t < STG; t++){
                float dv = sD[bf][t*DD + d];
                float xv = sX[bf][t*DD + d];
                sd += dv;
                float r  = ex2f(dv * a20);
                float r2 = r * r;
                ull e  = pk2(r, r2);
                ull rr = pk2(r2, r2);
                ull xpk = pk2(xv, xv);
                const ulonglong2* bt4 = (const ulonglong2*)(&sB[bf][t*NS]);
                ulonglong2 bv0 = bt4[0], bv1 = bt4[1], bv2 = bt4[2], bv3 = bt4[3];
                ull btv[8] = {bv0.x, bv0.y, bv1.x, bv1.y, bv2.x, bv2.y, bv3.x, bv3.y};
                #pragma unroll
                for (int q = 0; q < 8; q++){
                    ull p = mul2(btv[q], xpk);
                    h[q] = fma2(e, add2(h[q], p), neg2(p));
                    if (q < 7) e = mul2(e, rr);
                }
            }
            __syncthreads();
            if (s + 2 < NSTG) load_stage(s+2, bf);
        }
        ull* he = (ull*)(g_hend + base);
        #pragma unroll
        for (int q = 0; q < 8; q++) he[q] = h[q];
        float rho  = ex2f(a20 * sd);
        float rho2 = rho * rho;
        ull pe  = pk2(rho, rho2);
        ull prr = pk2(rho2, rho2);
        ull* pg = (ull*)(g_P + base);
        #pragma unroll
        for (int q = 0; q < 8; q++){
            pg[q] = pe;
            if (q < 7) pe = mul2(pe, prr);
        }
    } else {
        float A2[NS], iA[NS], h[NS];
        const float4* a4 = (const float4*)(g_A2 + d*NS);
        const float4* i4 = (const float4*)(g_invA + d*NS);
        #pragma unroll
        for (int q = 0; q < 4; q++){
            float4 a = a4[q]; float4 ii = i4[q];
            A2[4*q+0]=a.x; A2[4*q+1]=a.y; A2[4*q+2]=a.z; A2[4*q+3]=a.w;
            iA[4*q+0]=ii.x; iA[4*q+1]=ii.y; iA[4*q+2]=ii.z; iA[4*q+3]=ii.w;
        }
        #pragma unroll
        for (int n = 0; n < NS; n++) h[n] = 0.f;
        float sd = 0.f;
        for (int s = 0; s < NSTG; s++){
            if (s < NSTG-1) cpa_wait<1>(); else cpa_wait<0>();
            __syncthreads();
            int bf = s & 1;
            for (int t = 0; t < STG; t++){
                float dv = sD[bf][t*DD + d];
                float xv = sX[bf][t*DD + d];
                sd += dv;
                const float* bt = &sB[bf][t*NS];
                #pragma unroll
                for (int n = 0; n < NS; n++){
                    float e = ex2f(dv * A2[n]);
                    float p = iA[n] * (bt[n] * xv);
                    h[n] = fmaf(e, h[n] + p, -p);
                }
            }
            __syncthreads();
            if (s + 2 < NSTG) load_stage(s+2, bf);
        }
        #pragma unroll
        for (int n = 0; n < NS; n++){
            g_hend[base+n] = h[n];
            g_P[base+n]    = ex2f(A2[n] * sd);
        }
    }
}

// ---------------- pass 2: inter-chunk prefix -> h0 per chunk -------------
// 64 blocks x 256 threads; batched register tiles.
__global__ __launch_bounds__(256) void combine_kernel()
{
    int tid = blockIdx.x*256 + threadIdx.x;          // 16384 = B*D*N
    int b  = tid >> 10;
    int dn = tid & 1023;
    size_t base = (size_t)b*CC*1024 + dn;
    float h = 0.f;
    #pragma unroll
    for (int tile = 0; tile < CC/16; tile++){
        float P[16], E[16];
        #pragma unroll
        for (int j = 0; j < 16; j++){
            size_t o = base + (size_t)(tile*16 + j)*1024;
            P[j] = g_P[o];
            E[j] = g_hend[o];
        }
        #pragma unroll
        for (int j = 0; j < 16; j++){
            size_t o = base + (size_t)(tile*16 + j)*1024;
            g_h0[o] = h;
            h = fmaf(P[j], h, E[j]);
        }
    }
}

// ---------------- pass 3: re-run recursion with true h0, emit y ----------
__global__ __launch_bounds__(64) void scan3_kernel(const float* __restrict__ x,
    const float* __restrict__ Dskip, float* __restrict__ out)
{
    __shared__ __align__(16) float sD[2][STG*DD];
    __shared__ __align__(16) float sX[2][STG*DD];
    __shared__ __align__(16) float sB[2][STG*NS];
    __shared__ __align__(16) float sC[2][STG*NS];
    int b = blockIdx.y, c = blockIdx.x, d = threadIdx.x;
    size_t t0 = (size_t)b*LL + (size_t)c*LC;

    const float* dg = g_delta + t0*DD;
    const float* xg = x       + t0*DD;
    const float* bg = g_Bt    + t0*NS;
    const float* cg = g_Ct    + t0*NS;

    auto load_stage = [&](int s, int bf){
        unsigned aD = (unsigned)__cvta_generic_to_shared(&sD[bf][0]);
        unsigned aX = (unsigned)__cvta_generic_to_shared(&sX[bf][0]);
        unsigned aB = (unsigned)__cvta_generic_to_shared(&sB[bf][0]);
        unsigned aC = (unsigned)__cvta_generic_to_shared(&sC[bf][0]);
        const float* dsrc = dg + (size_t)s*STG*DD;
        const float* xsrc = xg + (size_t)s*STG*DD;
        const float* bsrc = bg + (size_t)s*STG*NS;
        const float* csrc = cg + (size_t)s*STG*NS;
        #pragma unroll
        for (int i = 0; i < (STG*DD/4)/64; i++){
            cpa16(aD + (d + i*64)*16, dsrc + (d + i*64)*4);
            cpa16(aX + (d + i*64)*16, xsrc + (d + i*64)*4);
        }
        #pragma unroll
        for (int i = 0; i < (STG*NS/4)/64; i++){
            cpa16(aB + (d + i*64)*16, bsrc + (d + i*64)*4);
            cpa16(aC + (d + i*64)*16, csrc + (d + i*64)*4);
        }
        cpa_commit();
    };

    load_stage(0, 0);
    load_stage(1, 1);

    size_t hb = (((size_t)(b*CC + c))*DD + d)*NS;
    float dsk = Dskip[d];
    bool write_y = (g_ident == 0);

    float* yp = g_y + t0*DD + d;
    float* op = out + t0*DD + d;

    if (g_fast){
        float a20 = g_A2row[0];
        ull h[4+4];
        const ull* h4 = (const ull*)(g_h0 + hb);
        #pragma unroll
        for (int q = 0; q < 8; q++) h[q] = h4[q];

        for (int s = 0; s < NSTG; s++){
            if (s < NSTG-1) cpa_wait<1>(); else cpa_wait<0>();
            __syncthreads();
            int bf = s & 1;
            #pragma unroll 2
            for (int tl = 0; tl < STG; tl++){
                int t = s*STG + tl;
                float dv = sD[bf][tl*DD + d];
                float xv = sX[bf][tl*DD + d];
                float r  = ex2f(dv * a20);
                float r2 = r * r;
                ull e  = pk2(r, r2);
                ull rr = pk2(r2, r2);
                ull xpk = pk2(xv, xv);
                const ulonglong2* bt4 = (const ulonglong2*)(&sB[bf][tl*NS]);
                const ulonglong2* ct4 = (const ulonglong2*)(&sC[bf][tl*NS]);
                ulonglong2 bv0 = bt4[0], bv1 = bt4[1], bv2 = bt4[2], bv3 = bt4[3];
                ulonglong2 cv0 = ct4[0], cv1 = ct4[1], cv2 = ct4[2], cv3 = ct4[3];
                ull btv[8] = {bv0.x, bv0.y, bv1.x, bv1.y, bv2.x, bv2.y, bv3.x, bv3.y};
                ull ctv[8] = {cv0.x, cv0.y, cv1.x, cv1.y, cv2.x, cv2.y, cv3.x, cv3.y};
                ull y2 = 0;
                #pragma unroll
                for (int q = 0; q < 8; q++){
                    ull p = mul2(btv[q], xpk);
                    h[q] = fma2(e, add2(h[q], p), neg2(p));
                    y2 = fma2(ctv[q], h[q], y2);
                    if (q < 7) e = mul2(e, rr);
                }
                float ylo, yhi;
                upk2(ylo, yhi, y2);
                float y = fmaf(dsk, xv, ylo + yhi);
                op[(size_t)t*DD] = y;
                if (write_y) yp[(size_t)t*DD] = y;
            }
            __syncthreads();
            if (s + 2 < NSTG) load_stage(s+2, bf);
        }
    } else {
        float A2[NS], iA[NS], h[NS];
        const float4* a4 = (const float4*)(g_A2 + d*NS);
        const float4* i4 = (const float4*)(g_invA + d*NS);
        #pragma unroll
        for (int q = 0; q < 4; q++){
            float4 a = a4[q]; float4 ii = i4[q];
            A2[4*q+0]=a.x; A2[4*q+1]=a.y; A2[4*q+2]=a.z; A2[4*q+3]=a.w;
            iA[4*q+0]=ii.x; iA[4*q+1]=ii.y; iA[4*q+2]=ii.z; iA[4*q+3]=ii.w;
        }
        const float4* h4 = (const float4*)(g_h0 + hb);
        #pragma unroll
        for (int q = 0; q < 4; q++){
            float4 v = h4[q];
            h[4*q+0]=v.x; h[4*q+1]=v.y; h[4*q+2]=v.z; h[4*q+3]=v.w;
        }
        for (int s = 0; s < NSTG; s++){
            if (s < NSTG-1) cpa_wait<1>(); else cpa_wait<0>();
            __syncthreads();
            int bf = s & 1;
            for (int tl = 0; tl < STG; tl++){
                int t = s*STG + tl;
                float dv = sD[bf][tl*DD + d];
                float xv = sX[bf][tl*DD + d];
                const float* bt = &sB[bf][tl*NS];
                const float* ct = &sC[bf][tl*NS];
                float y = dsk * xv;
                #pragma unroll
                for (int n = 0; n < NS; n++){
                    float e = ex2f(dv * A2[n]);
                    float p = iA[n] * (bt[n] * xv);
                    h[n] = fmaf(e, h[n] + p, -p);
                    y = fmaf(ct[n], h[n], y);
                }
                op[(size_t)t*DD] = y;
                if (write_y) yp[(size_t)t*DD] = y;
            }
            __syncthreads();
            if (s + 2 < NSTG) load_stage(s+2, bf);
        }
    }
}

// ---------------- final W_out GEMM (persistent; skipped when W_out == I) --
__global__ __launch_bounds__(256) void outgemm_kernel(const float* __restrict__ Wout,
    const float* __restrict__ bout, float* __restrict__ out)
{
    if (g_ident) return;
    __shared__ float Wt[64*64];
    __shared__ float ys[8][64];
    int tid = threadIdx.x;
    for (int i = tid; i < 4096; i += 256){
        int k = i >> 6, e = i & 63;
        Wt[k*64 + e] = Wout[e*64 + k];
    }
    __syncthreads();
    int warp = tid >> 5, lane = tid & 31;
    for (int blk = blockIdx.x; blk < NPROJ; blk += gridDim.x){
        size_t tokBase = (size_t)blk * 64;
        for (int tk = 0; tk < 8; tk++){
            size_t tg = tokBase + warp*8 + tk;
            ys[warp][lane]      = g_y[tg*64 + lane];
            ys[warp][lane + 32] = g_y[tg*64 + lane + 32];
            __syncwarp();
            float a0 = bout[lane], a1 = bout[lane+32];
            #pragma unroll
            for (int k = 0; k < 64; k++){
                float yv = ys[warp][k];
                a0 = fmaf(yv, Wt[k*64 + lane],      a0);
                a1 = fmaf(yv, Wt[k*64 + lane + 32], a1);
            }
            __syncwarp();
            out[tg*64 + lane]      = a0;
            out[tg*64 + lane + 32] = a1;
        }
    }
}

// ---------------- launch ----------------
extern "C" void kernel_launch(void* const* d_in, const int* in_sizes, int n_in,
                              void* d_out, int out_size)
{
    const float* x     = (const float*)d_in[0];
    const float* A_log = (const float*)d_in[1];
    const float* Dskip = (const float*)d_in[2];
    const float* Wout  = (const float*)d_in[3];
    const float* bout  = (const float*)d_in[4];
    const float* Wd    = (const float*)d_in[5];
    const float* bd    = (const float*)d_in[6];
    const float* WB    = (const float*)d_in[7];
    const float* WC    = (const float*)d_in[8];
    float* out = (float*)d_out;

    proj_kernel<<<NPROJ + 2, 256>>>(x, Wd, bd, WB, WC, A_log, Wout, bout);
    dim3 g(CC, BB);
    scan1_kernel<<<g, 64>>>(x);
    combine_kernel<<<64, 256>>>();
    scan3_kernel<<<g, 64>>>(x, Dskip, out);
    outgemm_kernel<<<148, 256>>>(Wout, bout, out);
}